// round 16
// baseline (speedup 1.0000x reference)
#include <cuda_runtime.h>
#include <cuda_bf16.h>
#include <cuda_fp16.h>
#include <cstdint>

#define B_DIM 4096
#define DIN   4096
#define DBN   32768
#define KSEL  64
#define CAND  80
#define BUF_CAP 1024
#define L2_CAP 256
#define FILTER_KEY 0xC000u   // monotonic key of +2.0 (bf16)

// ---------------- scratch (device globals: allocation-free) ----------------
__device__ __half        g_xh[(size_t)B_DIM * DIN];   // 32 MB  (GEMM A, fp16)
__device__ __half        g_wh[(size_t)DBN * DIN];     // 256 MB (GEMM B + decode, fp16)
__device__ __nv_bfloat16 g_a1[(size_t)B_DIM * DBN];   // 256 MB (bf16 scores)

// ---------------- K0: fp32 -> fp16 convert (EXACT R15) ----------------
__global__ void convert_kernel(const float* __restrict__ x, const float* __restrict__ w) {
    size_t nx = (size_t)B_DIM * DIN / 4;
    size_t nw = (size_t)DBN * DIN / 4;
    size_t stride = (size_t)gridDim.x * blockDim.x;
    for (size_t t = (size_t)blockIdx.x * blockDim.x + threadIdx.x; t < nx + nw; t += stride) {
        if (t < nx) {
            float4 v = ((const float4*)x)[t];
            __half2* o = reinterpret_cast<__half2*>(g_xh);
            o[2 * t]     = __floats2half2_rn(v.x, v.y);
            o[2 * t + 1] = __floats2half2_rn(v.z, v.w);
        } else {
            size_t u = t - nx;
            float4 v = ((const float4*)w)[u];
            __half2* o = reinterpret_cast<__half2*>(g_wh);
            o[2 * u]     = __floats2half2_rn(v.x, v.y);
            o[2 * u + 1] = __floats2half2_rn(v.z, v.w);
        }
    }
}

// ---------------- K1: fp16-input encode GEMM (EXACT R15) ----------------
__device__ __forceinline__ unsigned sw_off(int row, int c) {
    return (unsigned)(row * 64 + ((c ^ ((row >> 1) & 3)) << 4));
}

__global__ void __launch_bounds__(256) encode_gemm(const float* __restrict__ b_enc) {
    const int m0 = blockIdx.x * 128;
    const int n0 = blockIdx.y * 128;

    __shared__ __align__(16) __half sA[2][128 * 32];
    __shared__ __align__(16) __half sB[2][128 * 32];

    const int tid = threadIdx.x;
    const int wid = tid >> 5, lane = tid & 31;
    const int wm = wid >> 2, wn = wid & 3;

    unsigned sA_base = (unsigned)__cvta_generic_to_shared(&sA[0][0]);
    unsigned sB_base = (unsigned)__cvta_generic_to_shared(&sB[0][0]);

    const __half* gA = g_xh + (size_t)m0 * DIN;
    const __half* gB = g_wh + (size_t)n0 * DIN;

    float acc[4][4][4];
#pragma unroll
    for (int i = 0; i < 4; i++)
#pragma unroll
        for (int j = 0; j < 4; j++)
#pragma unroll
            for (int r = 0; r < 4; r++) acc[i][j][r] = 0.f;

#define LOAD_TILE(buf, kt)                                                              \
    do {                                                                                \
        _Pragma("unroll")                                                               \
        for (int _i = 0; _i < 2; _i++) {                                                \
            int cid = tid + 256 * _i;                                                   \
            int row = cid >> 2, c = cid & 3;                                            \
            unsigned off = sw_off(row, c);                                              \
            const __half* srcA = gA + (size_t)row * DIN + (kt) + c * 8;                 \
            const __half* srcB = gB + (size_t)row * DIN + (kt) + c * 8;                 \
            unsigned da = sA_base + (buf) * 8192u + off;                                \
            unsigned db = sB_base + (buf) * 8192u + off;                                \
            asm volatile("cp.async.cg.shared.global [%0],[%1],16;\n" ::"r"(da), "l"(srcA)); \
            asm volatile("cp.async.cg.shared.global [%0],[%1],16;\n" ::"r"(db), "l"(srcB)); \
        }                                                                               \
        asm volatile("cp.async.commit_group;\n");                                      \
    } while (0)

    LOAD_TILE(0, 0);
    const int NT = DIN / 32;
    for (int t = 0; t < NT; t++) {
        if (t + 1 < NT) {
            LOAD_TILE((t + 1) & 1, (t + 1) * 32);
            asm volatile("cp.async.wait_group 1;\n");
        } else {
            asm volatile("cp.async.wait_group 0;\n");
        }
        __syncthreads();
        const int buf = t & 1;
#pragma unroll
        for (int ks = 0; ks < 2; ks++) {
            unsigned a[4][4];
#pragma unroll
            for (int i = 0; i < 4; i++) {
                int row = wm * 64 + i * 16 + (lane & 7) + ((lane >> 3) & 1) * 8;
                int c   = ks * 2 + (lane >> 4);
                unsigned addr = sA_base + buf * 8192u + sw_off(row, c);
                asm volatile("ldmatrix.sync.aligned.m8n8.x4.shared.b16 {%0,%1,%2,%3},[%4];\n"
                             : "=r"(a[i][0]), "=r"(a[i][1]), "=r"(a[i][2]), "=r"(a[i][3])
                             : "r"(addr));
            }
            unsigned b[4][2];
#pragma unroll
            for (int jj = 0; jj < 2; jj++) {
                int row = wn * 32 + jj * 16 + ((lane >> 4) & 1) * 8 + (lane & 7);
                int c   = ks * 2 + ((lane >> 3) & 1);
                unsigned addr = sB_base + buf * 8192u + sw_off(row, c);
                unsigned r0, r1, r2, r3;
                asm volatile("ldmatrix.sync.aligned.m8n8.x4.shared.b16 {%0,%1,%2,%3},[%4];\n"
                             : "=r"(r0), "=r"(r1), "=r"(r2), "=r"(r3)
                             : "r"(addr));
                b[2 * jj][0] = r0; b[2 * jj][1] = r1;
                b[2 * jj + 1][0] = r2; b[2 * jj + 1][1] = r3;
            }
#pragma unroll
            for (int i = 0; i < 4; i++)
#pragma unroll
                for (int j = 0; j < 4; j++) {
                    asm volatile(
                        "mma.sync.aligned.m16n8k16.row.col.f32.f16.f16.f32 "
                        "{%0,%1,%2,%3},{%4,%5,%6,%7},{%8,%9},{%0,%1,%2,%3};\n"
                        : "+f"(acc[i][j][0]), "+f"(acc[i][j][1]),
                          "+f"(acc[i][j][2]), "+f"(acc[i][j][3])
                        : "r"(a[i][0]), "r"(a[i][1]), "r"(a[i][2]), "r"(a[i][3]),
                          "r"(b[j][0]), "r"(b[j][1]));
                }
        }
        __syncthreads();
    }
#undef LOAD_TILE

    const int mrow = m0 + wm * 64;
    const int ncol = n0 + wn * 32;
#pragma unroll
    for (int i = 0; i < 4; i++) {
#pragma unroll
        for (int j = 0; j < 4; j++) {
            int r  = mrow + i * 16 + (lane >> 2);
            int cc = ncol + j * 8 + (lane & 3) * 2;
            float be0 = __ldg(&b_enc[cc]);
            float be1 = __ldg(&b_enc[cc + 1]);
            __nv_bfloat162 v0 = __floats2bfloat162_rn(acc[i][j][0] + be0, acc[i][j][1] + be1);
            __nv_bfloat162 v1 = __floats2bfloat162_rn(acc[i][j][2] + be0, acc[i][j][3] + be1);
            *reinterpret_cast<__nv_bfloat162*>(&g_a1[(size_t)r * DBN + cc])       = v0;
            *reinterpret_cast<__nv_bfloat162*>(&g_a1[(size_t)(r + 8) * DBN + cc]) = v1;
        }
    }
}

// ---------------- K2: merged select + exact rescore + top-64 + decode ----------------
// Phase 1 (select): read a1 row, filter >= 2.0, 2048-bin select of top-CAND -> s_cand.
// Phase 2 (rescore+decode): smem pool is re-used for sx; exact Kahan/fp64 rescore of
// the CAND candidates, exact top-64, fp16-weight decode.
// smem pool layout (phase 1): buf[1024] | hist[2048] | part[256] | list2[256]  = 14.3KB
//                  (phase 2): sx = float[4096]                                 = 16KB

__device__ __forceinline__ unsigned fkey16(unsigned u) {
    u &= 0xFFFFu;
    return (u & 0x8000u) ? ((~u) & 0xFFFFu) : (u | 0x8000u);  // order-preserving
}

__global__ void __launch_bounds__(256) select_rescore_decode(
    const float* __restrict__ x, const float* __restrict__ W,
    const float* __restrict__ b_enc, const float* __restrict__ b_dec,
    float* __restrict__ out) {
    const int row = blockIdx.x;
    const int tid = threadIdx.x;
    const int wid = tid >> 5, lane = tid & 31;

    __shared__ __align__(16) unsigned pool[4096];   // 16 KB, phase-unioned
    __shared__ int    s_cand[CAND];
    __shared__ double sval[CAND];
    __shared__ float  sv[KSEL];
    __shared__ int    si[KSEL];
    __shared__ int    bcnt, mcnt, cnt;
    __shared__ unsigned s_tbin;

    unsigned* buf   = pool;            // [0, 1024)
    unsigned* hist  = pool + 1024;     // [1024, 3072)
    unsigned* part  = pool + 3072;     // [3072, 3328)
    unsigned* list2 = pool + 3328;     // [3328, 3584)

    // ---------------- phase 1: candidate selection ----------------
    if (tid == 0) { bcnt = 0; mcnt = 0; cnt = 0; }
    for (int i = tid; i < 2048; i += 256) hist[i] = 0;
    __syncthreads();

    const uint4* p4 = reinterpret_cast<const uint4*>(g_a1 + (size_t)row * DBN);
#pragma unroll 4
    for (int j = 0; j < 8; j++) {
        int vi = tid + 256 * j;
        uint4 v0 = p4[2 * vi];
        uint4 v1 = p4[2 * vi + 1];
        unsigned w[8] = {v0.x, v0.y, v0.z, v0.w, v1.x, v1.y, v1.z, v1.w};
        int base = vi * 16;
#pragma unroll
        for (int q = 0; q < 8; q++) {
            unsigned k0 = fkey16(w[q]);
            unsigned k1 = fkey16(w[q] >> 16);
            if (k0 >= FILTER_KEY) {
                int pos = atomicAdd(&bcnt, 1);
                if (pos < BUF_CAP) buf[pos] = (k0 << 16) | (unsigned)(base + 2 * q);
            }
            if (k1 >= FILTER_KEY) {
                int pos = atomicAdd(&bcnt, 1);
                if (pos < BUF_CAP) buf[pos] = (k1 << 16) | (unsigned)(base + 2 * q + 1);
            }
        }
    }
    __syncthreads();

    bool selected = false;
    if (bcnt >= CAND && bcnt <= BUF_CAP) {
        // fast path: 2048 bins, 2 bf16 codes per bin
        const int n = bcnt;
        for (int e = tid; e < n; e += 256) {
            unsigned bin = ((buf[e] >> 16) - FILTER_KEY) >> 1;
            if (bin > 2047u) bin = 2047u;
            atomicAdd(&hist[bin], 1u);
        }
        __syncthreads();
        unsigned ps = 0;
#pragma unroll
        for (int b = 0; b < 8; b++) ps += hist[tid * 8 + b];
        part[tid] = ps;
        __syncthreads();
        if (tid == 0) {
            unsigned cum = 0;
            int g = 255;
            for (; g > 0; g--) {
                if (cum + part[g] >= CAND) break;
                cum += part[g];
            }
            int b = g * 8 + 7;
            for (; b > 0; b--) {
                unsigned c = hist[b];
                if (cum + c >= CAND) break;
                cum += c;
            }
            s_tbin = (unsigned)b;
        }
        __syncthreads();
        const unsigned tb = s_tbin;
        for (int e = tid; e < n; e += 256) {
            const unsigned pe = buf[e];
            unsigned bin = ((pe >> 16) - FILTER_KEY) >> 1;
            if (bin > 2047u) bin = 2047u;
            if (bin >= tb) {
                int pos = atomicAdd(&mcnt, 1);
                if (pos < L2_CAP) list2[pos] = pe;
            }
        }
        __syncthreads();
        if (mcnt <= L2_CAP) {
            const int m = mcnt;   // >= CAND by construction
            for (int e = tid; e < m; e += 256) {
                const unsigned pe = list2[e];
                int rank = 0;
                for (int j2 = 0; j2 < m; j2++) rank += (list2[j2] > pe);
                if (rank < CAND) s_cand[rank] = (int)(pe & 0xFFFFu);
            }
            selected = true;
        }
        __syncthreads();
    }

    if (!selected) {
        // fallback: coarse 2048-bin histogram over the FULL key range (key>>5),
        // collect >= tie-bin into buf (<=1024), O(n^2) rank. Distribution-free.
        for (int i = tid; i < 2048; i += 256) hist[i] = 0;
        if (tid == 0) bcnt = 0;
        __syncthreads();
#pragma unroll 4
        for (int j = 0; j < 8; j++) {
            int vi = tid + 256 * j;
            uint4 v0 = p4[2 * vi];
            uint4 v1 = p4[2 * vi + 1];
            unsigned w[8] = {v0.x, v0.y, v0.z, v0.w, v1.x, v1.y, v1.z, v1.w};
#pragma unroll
            for (int q = 0; q < 8; q++) {
                atomicAdd(&hist[fkey16(w[q]) >> 5], 1u);
                atomicAdd(&hist[fkey16(w[q] >> 16) >> 5], 1u);
            }
        }
        __syncthreads();
        unsigned ps = 0;
#pragma unroll
        for (int b = 0; b < 8; b++) ps += hist[tid * 8 + b];
        part[tid] = ps;
        __syncthreads();
        if (tid == 0) {
            unsigned cum = 0;
            int g = 255;
            for (; g > 0; g--) {
                if (cum + part[g] >= CAND) break;
                cum += part[g];
            }
            int b = g * 8 + 7;
            for (; b > 0; b--) {
                unsigned c = hist[b];
                if (cum + c >= CAND) break;
                cum += c;
            }
            s_tbin = (unsigned)b;
        }
        __syncthreads();
        const unsigned tb = s_tbin;
#pragma unroll 4
        for (int j = 0; j < 8; j++) {
            int vi = tid + 256 * j;
            uint4 v0 = p4[2 * vi];
            uint4 v1 = p4[2 * vi + 1];
            unsigned w[8] = {v0.x, v0.y, v0.z, v0.w, v1.x, v1.y, v1.z, v1.w};
            int base = vi * 16;
#pragma unroll
            for (int q = 0; q < 8; q++) {
                unsigned k0 = fkey16(w[q]);
                unsigned k1 = fkey16(w[q] >> 16);
                if ((k0 >> 5) >= tb) {
                    int pos = atomicAdd(&bcnt, 1);
                    if (pos < BUF_CAP) buf[pos] = (k0 << 16) | (unsigned)(base + 2 * q);
                }
                if ((k1 >> 5) >= tb) {
                    int pos = atomicAdd(&bcnt, 1);
                    if (pos < BUF_CAP) buf[pos] = (k1 << 16) | (unsigned)(base + 2 * q + 1);
                }
            }
        }
        __syncthreads();
        const int n2 = bcnt < BUF_CAP ? bcnt : BUF_CAP;
        for (int e = tid; e < n2; e += 256) {
            const unsigned pe = buf[e];
            int rank = 0;
            for (int j2 = 0; j2 < n2; j2++) rank += (buf[j2] > pe);
            if (rank < CAND) s_cand[rank] = (int)(pe & 0xFFFFu);
        }
        __syncthreads();
    }

    // ---------------- phase 2: exact rescore + top-64 + decode ----------------
    // pool is re-used as sx (float[4096]); s_cand/sval persist separately.
    float* sx = reinterpret_cast<float*>(pool);
    {
        const float4* xg  = reinterpret_cast<const float4*>(x + (size_t)row * DIN);
        float4*       sx4 = reinterpret_cast<float4*>(sx);
        for (int i = tid; i < DIN / 4; i += 256) sx4[i] = xg[i];
    }
    __syncthreads();

    for (int c = wid; c < CAND; c += 8) {
        const int idx = s_cand[c];
        const float4* wv = reinterpret_cast<const float4*>(W + (size_t)idx * DIN);
        const float4* sx4 = reinterpret_cast<const float4*>(sx);
        float s0 = 0.f, c0 = 0.f, s1 = 0.f, c1 = 0.f;
#define ACC(ss, cc, aa, bb)                              \
        {                                                \
            float p = (aa) * (bb);                       \
            float e = __fmaf_rn((aa), (bb), -p);         \
            float t = ss + p;                            \
            cc += (ss - t) + p;                          \
            ss = t;                                      \
            cc += e;                                     \
        }
        for (int i = lane; i < DIN / 4; i += 32) {
            float4 w = wv[i], xx = sx4[i];
            ACC(s0, c0, w.x, xx.x) ACC(s1, c1, w.y, xx.y)
            ACC(s0, c0, w.z, xx.z) ACC(s1, c1, w.w, xx.w)
        }
#undef ACC
        double d = ((double)s0 + (double)c0) + ((double)s1 + (double)c1);
#pragma unroll
        for (int o = 16; o; o >>= 1) d += __shfl_xor_sync(0xFFFFFFFFu, d, o);
        if (lane == 0) sval[c] = d + (double)b_enc[idx];
    }
    __syncthreads();

    if (tid < CAND) {
        const double v = sval[tid];
        const int   ii = s_cand[tid];
        int greater = 0;
        for (int j = 0; j < CAND; j++) {
            double u = sval[j];
            if (u > v || (u == v && s_cand[j] < ii)) greater++;
        }
        if (greater < KSEL) {
            int slot = atomicAdd(&cnt, 1);
            sv[slot] = (float)v;
            si[slot] = ii;
        }
    }
    __syncthreads();

    const float4* bd = reinterpret_cast<const float4*>(b_dec);
    float4 acc[4];
#pragma unroll
    for (int s = 0; s < 4; s++) acc[s] = bd[tid + s * 256];

    for (int j = 0; j < KSEL; j++) {
        const float v = sv[j];
        const uint2* wr = reinterpret_cast<const uint2*>(g_wh + (size_t)si[j] * DIN);
#pragma unroll
        for (int s = 0; s < 4; s++) {
            uint2 hw = wr[tid + s * 256];
            float2 lo = __half22float2(*reinterpret_cast<__half2*>(&hw.x));
            float2 hi = __half22float2(*reinterpret_cast<__half2*>(&hw.y));
            acc[s].x += v * lo.x; acc[s].y += v * lo.y;
            acc[s].z += v * hi.x; acc[s].w += v * hi.y;
        }
    }
    float4* o = reinterpret_cast<float4*>(out + (size_t)row * DIN);
#pragma unroll
    for (int s = 0; s < 4; s++) o[tid + s * 256] = acc[s];
}

// ---------------- launch ----------------
extern "C" void kernel_launch(void* const* d_in, const int* in_sizes, int n_in,
                              void* d_out, int out_size) {
    const float* x     = (const float*)d_in[0];
    const float* W     = (const float*)d_in[1];
    const float* b_enc = (const float*)d_in[2];
    const float* b_dec = (const float*)d_in[3];
    float* out = (float*)d_out;

    convert_kernel<<<2368, 256>>>(x, W);

    dim3 g1(B_DIM / 128, DBN / 128);
    encode_gemm<<<g1, 256>>>(b_enc);

    select_rescore_decode<<<B_DIM, 256>>>(x, W, b_enc, b_dec, out);
}